// round 3
// baseline (speedup 1.0000x reference)
#include <cuda_runtime.h>
#include <math.h>

#define NN   128          // nodes
#define DD   256          // feature dim
#define TTH  512          // head length
#define AST  132          // adj smem stride (floats)
#define SST  20           // active-S smem stride (CH + 4)
#define CH   16           // active-column chunk
#define THREADS 256

#define SMEM_FLOATS (NN*AST + 2*NN*SST + CH*AST + DD + 8*NN + NN + NN + 8)
#define SMEM_BYTES  (SMEM_FLOATS * 4)

__global__ __launch_bounds__(THREADS, 2)
void graph_enc_kernel(const float* __restrict__ x,     // [B,128,256]
                      const float* __restrict__ adj,   // [B,128,128]
                      const int*   __restrict__ head,  // [B,512]
                      const float* __restrict__ linw,  // [256]
                      const float* __restrict__ bias,  // [1]
                      float* __restrict__ out_emb,     // [B,128,256]
                      float* __restrict__ out_adj)     // [B,128,128]
{
    extern __shared__ float sm[];
    float* sA   = sm;                    // adj [128][132]
    float* sSa  = sA  + NN*AST;          // active S cols (row chunk) [128][20]
    float* sSb  = sSa + NN*SST;          // active S cols (col chunk) [128][20]
    float* sQ   = sSb + NN*SST;          // Qa = Sa^T adj [16][132]
    float* sw   = sQ  + CH*AST;          // lin_w
    float* s_s  = sw  + DD;              // x @ w
    float* s_di = s_s + NN;              // deg^-1/2
    float* s_md = s_di+ NN;              // mask * di
    float* s_t  = s_md+ NN;              // di * s
    float* s_al = s_t + NN;              // alpha
    float* s_ca = s_al+ NN;              // cut_alpha
    float* s_iv = s_ca+ NN;              // 1/rowL1
    float* s_rs = s_iv+ NN;              // adj row sums
    int*   s_fl = (int*)(s_rs + NN);     // head flags
    int*   s_ac = s_fl + NN;             // active indices
    int*   s_cn = s_ac + NN;             // active count
    float* s_ct = (float*)(s_cn + 1);    // cut value

    const int tid  = threadIdx.x;
    const int bat  = blockIdx.x;
    const int lane = tid & 31;
    const int wrp  = tid >> 5;

    const float* xB = x   + (size_t)bat * NN * DD;
    const float* aB = adj + (size_t)bat * NN * NN;
    float* oE = out_emb + (size_t)bat * NN * DD;
    float* oA = out_adj + (size_t)bat * NN * NN;

    // ---- P0a: zero-fill ALL outputs up front (stores drain in background) ----
    {
        const float4 z4 = make_float4(0.f, 0.f, 0.f, 0.f);
        float4* oE4 = reinterpret_cast<float4*>(oE);   // 8192 float4
        float4* oA4 = reinterpret_cast<float4*>(oA);   // 4096 float4
        #pragma unroll
        for (int q = 0; q < 32; ++q) oE4[tid + q * THREADS] = z4;
        #pragma unroll
        for (int q = 0; q < 16; ++q) oA4[tid + q * THREADS] = z4;
    }

    // ---- P0b: init + load adj ----
    sw[tid] = linw[tid];
    if (tid < NN) s_fl[tid] = 0;
    if (tid == 0) { *s_cn = 0; *s_ct = 0.0f; }

    for (int t = tid; t < NN*NN/4; t += THREADS) {
        int i = t >> 5, f = t & 31;
        reinterpret_cast<float4*>(&sA[i * AST])[f] =
            reinterpret_cast<const float4*>(aB)[t];
    }
    __syncthreads();
    for (int t = tid; t < TTH; t += THREADS) s_fl[head[(size_t)bat*TTH + t]] = 1;

    // ---- P1: row sums + s=x@w + di, two rows per warp-iteration (MLP 16) ----
    for (int i = wrp; i < 64; i += 8) {
        const int i2 = i + 64;
        float xv1[8], xv2[8];
        const float* xr1 = xB + (size_t)i  * DD;
        const float* xr2 = xB + (size_t)i2 * DD;
        #pragma unroll
        for (int q = 0; q < 8; ++q) { xv1[q] = xr1[lane + q*32]; xv2[q] = xr2[lane + q*32]; }

        const float* r1 = &sA[i  * AST];
        const float* r2 = &sA[i2 * AST];
        float rs1 = r1[lane] + r1[lane+32] + r1[lane+64] + r1[lane+96];
        float rs2 = r2[lane] + r2[lane+32] + r2[lane+64] + r2[lane+96];

        float d1 = 0.f, d2 = 0.f;
        #pragma unroll
        for (int q = 0; q < 8; ++q) {
            const float wv = sw[lane + q*32];
            d1 = fmaf(xv1[q], wv, d1);
            d2 = fmaf(xv2[q], wv, d2);
        }
        #pragma unroll
        for (int o = 16; o; o >>= 1) {
            rs1 += __shfl_xor_sync(0xFFFFFFFFu, rs1, o);
            rs2 += __shfl_xor_sync(0xFFFFFFFFu, rs2, o);
            d1  += __shfl_xor_sync(0xFFFFFFFFu, d1,  o);
            d2  += __shfl_xor_sync(0xFFFFFFFFu, d2,  o);
        }
        if (lane == 0) {
            s_rs[i] = rs1;  s_s[i] = d1;
            s_rs[i2] = rs2; s_s[i2] = d2;
            float g1 = rs1 + 1.0f; if (g1 < 1.0f) g1 = 1.0f;
            float g2 = rs2 + 1.0f; if (g2 < 1.0f) g2 = 1.0f;
            float q1 = rsqrtf(g1), q2 = rsqrtf(g2);
            s_di[i]  = q1; s_md[i]  = (rs1 > 0.0f) ? q1 : 0.0f;
            s_di[i2] = q2; s_md[i2] = (rs2 > 0.0f) ? q2 : 0.0f;
        }
    }
    __syncthreads();
    if (tid < NN) s_t[tid] = s_di[tid] * s_s[tid];
    __syncthreads();

    // ---- P2: alpha = sigmoid((normA@s + bias)^2) via adj@t ----
    const float bv = bias[0];
    for (int i = wrp; i < NN; i += 8) {
        float acc = 0.0f;
        #pragma unroll
        for (int q = 0; q < 4; ++q) {
            int j = lane + q*32;
            acc = fmaf(sA[i*AST + j], s_t[j], acc);
        }
        #pragma unroll
        for (int o = 16; o; o >>= 1) acc += __shfl_xor_sync(0xFFFFFFFFu, acc, o);
        if (lane == 0) {
            float o2 = s_md[i] * (acc + s_di[i] * s_s[i]) + bv;
            float z  = o2 * o2;
            s_al[i]  = 1.0f / (1.0f + expf(-z));
        }
    }

    // ---- P3: unique count + exact rank select for cut ----
    int nu = __syncthreads_count(tid < NN && s_fl[tid]);
    int kidx = (int)ceilf((float)nu * 0.1f);     // k-1
    if (kidx < 0) kidx = 0;
    if (kidx > NN-1) kidx = NN-1;
    if (nu > 1 && tid < NN) {
        const float ai = s_al[tid];
        int r = 0;
        #pragma unroll 4
        for (int j = 0; j < NN; ++j) {
            float aj = s_al[j];
            r += (aj > ai) || (aj == ai && j < tid);
        }
        if (r == kidx) *s_ct = ai;
    }
    __syncthreads();
    const float cut = *s_ct;

    // ---- P4: cut_alpha + active compaction ----
    int pos = -1;
    if (tid < NN) {
        float cav = fmaxf(s_al[tid] + 1e-7f - cut, 0.0f);
        s_ca[tid] = cav;
        if (cav > 0.0f) pos = atomicAdd(s_cn, 1);
    }
    if (pos >= 0) s_ac[pos] = tid;
    __syncthreads();
    const int K = *s_cn;

    // ---- P5: row L1 inverse over active columns ----
    if (tid < NN) {
        const int i = tid;
        float r = 0.0f;
        for (int a = 0; a < K; ++a) {
            int ja = s_ac[a];
            float v = sA[i*AST + ja] + ((i == ja) ? 1.0f : 0.0f);
            r = fmaf(v, s_di[ja] * s_ca[ja], r);
        }
        r *= s_md[i];
        s_iv[i] = 1.0f / fmaxf(r, 1e-12f);
    }
    __syncthreads();

    // ---- chunked active GEMMs (typical: one chunk, K <= 16) ----
    const int nch = (K + CH - 1) / CH;
    for (int ac = 0; ac < nch; ++ac) {
        const int an0 = ac * CH;
        int cn = K - an0; if (cn > CH) cn = CH;

        __syncthreads();
        if (tid < NN) {
            const int i = tid;
            const float mi = s_md[i] * s_iv[i];
            #pragma unroll
            for (int a = 0; a < CH; ++a) {
                float v = 0.0f;
                if (a < cn) {
                    int ja = s_ac[an0 + a];
                    v = mi * (sA[i*AST + ja] + ((i == ja) ? 1.0f : 0.0f))
                           * (s_di[ja] * s_ca[ja]);
                }
                sSa[i*SST + a] = v;
            }
        }
        __syncthreads();

        // GEMM2': Qa[a][m] = sum_i Sa[i][a] * adj[i][m]  (warps 0-3; warps 4-7 skip ahead)
        if (tid < NN) {
            const int m = tid;
            float acc[CH];
            #pragma unroll
            for (int a = 0; a < CH; ++a) acc[a] = 0.0f;
            #pragma unroll 2
            for (int i = 0; i < NN; ++i) {
                const float av = sA[i*AST + m];
                const float4 w0 = *reinterpret_cast<float4*>(&sSa[i*SST + 0]);
                const float4 w1 = *reinterpret_cast<float4*>(&sSa[i*SST + 4]);
                const float4 w2 = *reinterpret_cast<float4*>(&sSa[i*SST + 8]);
                const float4 w3 = *reinterpret_cast<float4*>(&sSa[i*SST + 12]);
                acc[0]  = fmaf(w0.x, av, acc[0]);  acc[1]  = fmaf(w0.y, av, acc[1]);
                acc[2]  = fmaf(w0.z, av, acc[2]);  acc[3]  = fmaf(w0.w, av, acc[3]);
                acc[4]  = fmaf(w1.x, av, acc[4]);  acc[5]  = fmaf(w1.y, av, acc[5]);
                acc[6]  = fmaf(w1.z, av, acc[6]);  acc[7]  = fmaf(w1.w, av, acc[7]);
                acc[8]  = fmaf(w2.x, av, acc[8]);  acc[9]  = fmaf(w2.y, av, acc[9]);
                acc[10] = fmaf(w2.z, av, acc[10]); acc[11] = fmaf(w2.w, av, acc[11]);
                acc[12] = fmaf(w3.x, av, acc[12]); acc[13] = fmaf(w3.y, av, acc[13]);
                acc[14] = fmaf(w3.z, av, acc[14]); acc[15] = fmaf(w3.w, av, acc[15]);
            }
            #pragma unroll
            for (int a = 0; a < CH; ++a)
                if (a < cn) sQ[a*AST + m] = acc[a];
        }

        // GEMM1': emb[ja][d] = sum_i Sa[i][a] * x[i][d]  — front-batched x loads (MLP 8)
        {
            const int d = tid;
            float acc[CH];
            #pragma unroll
            for (int a = 0; a < CH; ++a) acc[a] = 0.0f;

            for (int i0 = 0; i0 < NN; i0 += 8) {
                float xv[8];
                #pragma unroll
                for (int u = 0; u < 8; ++u)
                    xv[u] = xB[(size_t)(i0 + u) * DD + d];
                #pragma unroll
                for (int u = 0; u < 8; ++u) {
                    const int i = i0 + u;
                    const float4 w0 = *reinterpret_cast<float4*>(&sSa[i*SST + 0]);
                    const float4 w1 = *reinterpret_cast<float4*>(&sSa[i*SST + 4]);
                    const float4 w2 = *reinterpret_cast<float4*>(&sSa[i*SST + 8]);
                    const float4 w3 = *reinterpret_cast<float4*>(&sSa[i*SST + 12]);
                    const float xu = xv[u];
                    acc[0]  = fmaf(w0.x, xu, acc[0]);  acc[1]  = fmaf(w0.y, xu, acc[1]);
                    acc[2]  = fmaf(w0.z, xu, acc[2]);  acc[3]  = fmaf(w0.w, xu, acc[3]);
                    acc[4]  = fmaf(w1.x, xu, acc[4]);  acc[5]  = fmaf(w1.y, xu, acc[5]);
                    acc[6]  = fmaf(w1.z, xu, acc[6]);  acc[7]  = fmaf(w1.w, xu, acc[7]);
                    acc[8]  = fmaf(w2.x, xu, acc[8]);  acc[9]  = fmaf(w2.y, xu, acc[9]);
                    acc[10] = fmaf(w2.z, xu, acc[10]); acc[11] = fmaf(w2.w, xu, acc[11]);
                    acc[12] = fmaf(w3.x, xu, acc[12]); acc[13] = fmaf(w3.y, xu, acc[13]);
                    acc[14] = fmaf(w3.z, xu, acc[14]); acc[15] = fmaf(w3.w, xu, acc[15]);
                }
            }
            #pragma unroll
            for (int a = 0; a < CH; ++a)
                if (a < cn) oE[(size_t)s_ac[an0 + a] * DD + d] = acc[a];
        }
        __syncthreads();   // sQ ready

        // GEMM3': new_adj[ja][jb] = sum_m Qa[a][m] * S[m][jb]
        if (nch == 1) {
            // fast path: Sb == Sa, no rebuild
            const int a  = tid >> 4;
            const int bq = tid & 15;
            float v = 0.0f;
            #pragma unroll 4
            for (int m = 0; m < NN; ++m)
                v = fmaf(sQ[a*AST + m], sSa[m*SST + bq], v);
            if (a < cn && bq < cn)
                oA[(size_t)s_ac[a] * NN + s_ac[bq]] = v;
        } else {
            for (int bc = 0; bc < nch; ++bc) {
                const int bn0 = bc * CH;
                int bn = K - bn0; if (bn > CH) bn = CH;

                __syncthreads();
                if (tid < NN) {
                    const int i = tid;
                    const float mi = s_md[i] * s_iv[i];
                    #pragma unroll
                    for (int bq = 0; bq < CH; ++bq) {
                        float v = 0.0f;
                        if (bq < bn) {
                            int jb = s_ac[bn0 + bq];
                            v = mi * (sA[i*AST + jb] + ((i == jb) ? 1.0f : 0.0f))
                                   * (s_di[jb] * s_ca[jb]);
                        }
                        sSb[i*SST + bq] = v;
                    }
                }
                __syncthreads();

                const int a  = tid >> 4;
                const int bq = tid & 15;
                float v = 0.0f;
                #pragma unroll 4
                for (int m = 0; m < NN; ++m)
                    v = fmaf(sQ[a*AST + m], sSb[m*SST + bq], v);
                if (a < cn && bq < bn)
                    oA[(size_t)s_ac[an0 + a] * NN + s_ac[bn0 + bq]] = v;
            }
        }
    }
}

extern "C" void kernel_launch(void* const* d_in, const int* in_sizes, int n_in,
                              void* d_out, int out_size)
{
    const float* x    = (const float*)d_in[0];   // [B,128,256]
    const float* adj  = (const float*)d_in[1];   // [B,128,128]
    const int*   head = (const int*)  d_in[2];   // [B,512]
    const float* lw   = (const float*)d_in[3];   // [1,256]
    const float* bs   = (const float*)d_in[4];   // [1]

    const int B = in_sizes[0] / (NN * DD);       // 512

    float* out_emb = (float*)d_out;                       // [B,128,256]
    float* out_adj = out_emb + (size_t)B * NN * DD;       // [B,128,128]

    cudaFuncSetAttribute(graph_enc_kernel,
                         cudaFuncAttributeMaxDynamicSharedMemorySize, SMEM_BYTES);
    graph_enc_kernel<<<B, THREADS, SMEM_BYTES>>>(x, adj, head, lw, bs, out_emb, out_adj);
}

// round 5
// speedup vs baseline: 1.5598x; 1.5598x over previous
#include <cuda_runtime.h>
#include <math.h>

#define NN   128
#define DD   256
#define TTH  512
#define AST  132          // sQ stride
#define SST  20           // sSa stride (CH+4)
#define CH   16
#define THREADS 256
#define BMAX 512

// scratch (K1 -> K2)
__device__ float g_t [BMAX * NN];   // di * (x@w)
__device__ float g_di[BMAX * NN];   // deg^-1/2
__device__ float g_md[BMAX * NN];   // mask * di

// ============================ K1: per-row stats ============================
__global__ __launch_bounds__(THREADS)
void k1_stats(const float* __restrict__ x, const float* __restrict__ adj,
              const float* __restrict__ linw)
{
    __shared__ float sw[DD];
    const int tid = threadIdx.x, lane = tid & 31, wrp = tid >> 5;
    const int bat = blockIdx.x;
    sw[tid] = linw[tid];
    __syncthreads();

    const float* xB = x   + (size_t)bat * NN * DD;
    const float* aB = adj + (size_t)bat * NN * NN;

    for (int i = wrp; i < 64; i += 8) {
        const int i2 = i + 64;
        float xv1[8], xv2[8], av1[4], av2[4];
        #pragma unroll
        for (int q = 0; q < 8; ++q) {
            xv1[q] = xB[(size_t)i  * DD + lane + q*32];
            xv2[q] = xB[(size_t)i2 * DD + lane + q*32];
        }
        #pragma unroll
        for (int q = 0; q < 4; ++q) {
            av1[q] = aB[(size_t)i  * NN + lane + q*32];
            av2[q] = aB[(size_t)i2 * NN + lane + q*32];
        }
        float rs1 = (av1[0]+av1[1]) + (av1[2]+av1[3]);
        float rs2 = (av2[0]+av2[1]) + (av2[2]+av2[3]);
        float d1 = 0.f, d2 = 0.f;
        #pragma unroll
        for (int q = 0; q < 8; ++q) {
            const float wv = sw[lane + q*32];
            d1 = fmaf(xv1[q], wv, d1);
            d2 = fmaf(xv2[q], wv, d2);
        }
        #pragma unroll
        for (int o = 16; o; o >>= 1) {
            rs1 += __shfl_xor_sync(0xFFFFFFFFu, rs1, o);
            rs2 += __shfl_xor_sync(0xFFFFFFFFu, rs2, o);
            d1  += __shfl_xor_sync(0xFFFFFFFFu, d1,  o);
            d2  += __shfl_xor_sync(0xFFFFFFFFu, d2,  o);
        }
        if (lane == 0) {
            float g1 = rs1 + 1.0f; if (g1 < 1.0f) g1 = 1.0f;
            float g2 = rs2 + 1.0f; if (g2 < 1.0f) g2 = 1.0f;
            float q1 = rsqrtf(g1), q2 = rsqrtf(g2);
            g_di[bat*NN + i]  = q1;
            g_di[bat*NN + i2] = q2;
            g_md[bat*NN + i]  = (rs1 > 0.0f) ? q1 : 0.0f;
            g_md[bat*NN + i2] = (rs2 > 0.0f) ? q2 : 0.0f;
            g_t [bat*NN + i]  = q1 * d1;
            g_t [bat*NN + i2] = q2 * d2;
        }
    }
}

// ============================ K2: main ============================
__global__ __launch_bounds__(THREADS)
void k2_main(const float* __restrict__ x, const float* __restrict__ adj,
             const int* __restrict__ head, const float* __restrict__ bias,
             float* __restrict__ out_emb, float* __restrict__ out_adj)
{
    __shared__ float sSa[NN * SST];
    __shared__ float sQ [CH * AST];
    __shared__ float s_t[NN], s_di[NN], s_md[NN], s_al[NN], s_wa[NN], s_riv[NN];
    __shared__ int   s_fl[NN], s_ac[NN], s_wc[4];
    __shared__ float s_ct;

    const int tid = threadIdx.x, lane = tid & 31, wrp = tid >> 5;
    const int bat = blockIdx.x;

    const float* xB = x   + (size_t)bat * NN * DD;
    const float* aB = adj + (size_t)bat * NN * NN;
    float* oE = out_emb + (size_t)bat * NN * DD;
    float* oA = out_adj + (size_t)bat * NN * NN;

    // zero-fill this batch's outputs; stores drain under subsequent compute
    {
        const float4 z4 = make_float4(0.f, 0.f, 0.f, 0.f);
        float4* oE4 = reinterpret_cast<float4*>(oE);
        float4* oA4 = reinterpret_cast<float4*>(oA);
        #pragma unroll
        for (int q = 0; q < 32; ++q) oE4[tid + q * THREADS] = z4;
        #pragma unroll
        for (int q = 0; q < 16; ++q) oA4[tid + q * THREADS] = z4;
    }

    if (tid < NN) {
        s_t [tid] = g_t [bat*NN + tid];
        s_di[tid] = g_di[bat*NN + tid];
        s_md[tid] = g_md[bat*NN + tid];
        s_fl[tid] = 0;
    }
    if (tid == 0) s_ct = 0.0f;
    __syncthreads();
    for (int tv = tid; tv < TTH; tv += THREADS) s_fl[head[(size_t)bat*TTH + tv]] = 1;

    // ---- alpha = sigmoid((md*(adj@t + t) + bias)^2), adj rows from L2 ----
    const float bv = bias[0];
    for (int i = wrp; i < 64; i += 8) {
        const int i2 = i + 64;
        float a1[4], a2[4];
        #pragma unroll
        for (int q = 0; q < 4; ++q) {
            a1[q] = aB[(size_t)i  * NN + lane + q*32];
            a2[q] = aB[(size_t)i2 * NN + lane + q*32];
        }
        float c1 = 0.f, c2 = 0.f;
        #pragma unroll
        for (int q = 0; q < 4; ++q) {
            const float tv = s_t[lane + q*32];
            c1 = fmaf(a1[q], tv, c1);
            c2 = fmaf(a2[q], tv, c2);
        }
        #pragma unroll
        for (int o = 16; o; o >>= 1) {
            c1 += __shfl_xor_sync(0xFFFFFFFFu, c1, o);
            c2 += __shfl_xor_sync(0xFFFFFFFFu, c2, o);
        }
        if (lane == 0) {
            float o1 = s_md[i ] * (c1 + s_t[i ]) + bv;
            float o2 = s_md[i2] * (c2 + s_t[i2]) + bv;
            s_al[i ] = 1.0f / (1.0f + expf(-(o1*o1)));
            s_al[i2] = 1.0f / (1.0f + expf(-(o2*o2)));
        }
    }

    // ---- unique count + exact rank-select cut ----
    int nu = __syncthreads_count(tid < NN && s_fl[tid]);
    int kidx = (int)ceilf((float)nu * 0.1f);
    if (kidx < 0) kidx = 0;
    if (kidx > NN-1) kidx = NN-1;
    if (nu > 1 && tid < NN) {
        const float ai = s_al[tid];
        int r = 0;
        #pragma unroll 4
        for (int j = 0; j < NN; ++j) {
            float aj = s_al[j];
            r += (aj > ai) || (aj == ai && j < tid);
        }
        if (r == kidx) s_ct = ai;
    }
    __syncthreads();
    const float cut = s_ct;

    // ---- cut_alpha, col scale wa, deterministic ballot compaction ----
    bool act = false;
    unsigned bm = 0;
    if (tid < NN) {
        float ca = fmaxf(s_al[tid] + 1e-7f - cut, 0.0f);
        s_wa[tid] = s_di[tid] * ca;
        act = (ca > 0.0f);
        bm = __ballot_sync(0xFFFFFFFFu, act);
        if (lane == 0) s_wc[wrp] = __popc(bm);
    }
    __syncthreads();
    const int K = s_wc[0] + s_wc[1] + s_wc[2] + s_wc[3];
    if (tid < NN && act) {
        int off = 0;
        for (int w = 0; w < wrp; ++w) off += s_wc[w];
        s_ac[off + __popc(bm & ((1u << lane) - 1u))] = tid;
    }
    __syncthreads();

    // ---- riv = md / max(md*rowsum, 1e-12); cache first-chunk products ----
    if (tid < NN) {
        const int i = tid;
        const float* ar = aB + (size_t)i * NN;
        float r = 0.0f;
        int a = 0;
        for (; a + 4 <= K; a += 4) {
            int j0 = s_ac[a], j1 = s_ac[a+1], j2 = s_ac[a+2], j3 = s_ac[a+3];
            float v0 = ar[j0] + ((i == j0) ? 1.0f : 0.0f);
            float v1 = ar[j1] + ((i == j1) ? 1.0f : 0.0f);
            float v2 = ar[j2] + ((i == j2) ? 1.0f : 0.0f);
            float v3 = ar[j3] + ((i == j3) ? 1.0f : 0.0f);
            float u0 = v0 * s_wa[j0], u1 = v1 * s_wa[j1];
            float u2 = v2 * s_wa[j2], u3 = v3 * s_wa[j3];
            if (a+0 < CH) sSa[i*SST + a+0] = u0;
            if (a+1 < CH) sSa[i*SST + a+1] = u1;
            if (a+2 < CH) sSa[i*SST + a+2] = u2;
            if (a+3 < CH) sSa[i*SST + a+3] = u3;
            r += (u0 + u1) + (u2 + u3);
        }
        for (; a < K; ++a) {
            int j = s_ac[a];
            float u = (ar[j] + ((i == j) ? 1.0f : 0.0f)) * s_wa[j];
            if (a < CH) sSa[i*SST + a] = u;
            r += u;
        }
        for (int a2 = K; a2 < CH; ++a2) sSa[i*SST + a2] = 0.0f;
        float rl = s_md[i] * r;
        s_riv[i] = s_md[i] / fmaxf(rl, 1e-12f);
    }
    __syncthreads();

    // ---- chunked active GEMMs (typical: one chunk) ----
    const int nch = (K + CH - 1) / CH;
    for (int ac = 0; ac < nch; ++ac) {
        const int an0 = ac * CH;
        int cn = K - an0; if (cn > CH) cn = CH;

        if (ac == 0) {
            if (tid < NN) {
                const float rv = s_riv[tid];
                #pragma unroll
                for (int a = 0; a < CH; ++a) sSa[tid*SST + a] *= rv;
            }
        } else {
            __syncthreads();   // prior GEMM3 readers of sSa done
            if (tid < NN) {
                const int i = tid;
                const float* ar = aB + (size_t)i * NN;
                const float rv = s_riv[i];
                #pragma unroll
                for (int a = 0; a < CH; ++a) {
                    float v = 0.0f;
                    if (a < cn) {
                        int j = s_ac[an0 + a];
                        v = rv * (ar[j] + ((i == j) ? 1.0f : 0.0f)) * s_wa[j];
                    }
                    sSa[i*SST + a] = v;
                }
            }
        }
        __syncthreads();

        // GEMM2': Q[a][m] = sum_i Sa[i][a] * adj[i][m]   (tid<128, m=tid)
        if (tid < NN) {
            const int m = tid;
            float acc[CH];
            #pragma unroll
            for (int a = 0; a < CH; ++a) acc[a] = 0.0f;
            for (int i0 = 0; i0 < NN; i0 += 8) {
                float av[8];
                #pragma unroll
                for (int u = 0; u < 8; ++u)
                    av[u] = aB[(size_t)(i0 + u) * NN + m];
                #pragma unroll
                for (int u = 0; u < 8; ++u) {
                    const int i = i0 + u;
                    const float4 w0 = *reinterpret_cast<float4*>(&sSa[i*SST + 0]);
                    const float4 w1 = *reinterpret_cast<float4*>(&sSa[i*SST + 4]);
                    const float4 w2 = *reinterpret_cast<float4*>(&sSa[i*SST + 8]);
                    const float4 w3 = *reinterpret_cast<float4*>(&sSa[i*SST + 12]);
                    const float aw = av[u];
                    acc[0]  = fmaf(w0.x, aw, acc[0]);  acc[1]  = fmaf(w0.y, aw, acc[1]);
                    acc[2]  = fmaf(w0.z, aw, acc[2]);  acc[3]  = fmaf(w0.w, aw, acc[3]);
                    acc[4]  = fmaf(w1.x, aw, acc[4]);  acc[5]  = fmaf(w1.y, aw, acc[5]);
                    acc[6]  = fmaf(w1.z, aw, acc[6]);  acc[7]  = fmaf(w1.w, aw, acc[7]);
                    acc[8]  = fmaf(w2.x, aw, acc[8]);  acc[9]  = fmaf(w2.y, aw, acc[9]);
                    acc[10] = fmaf(w2.z, aw, acc[10]); acc[11] = fmaf(w2.w, aw, acc[11]);
                    acc[12] = fmaf(w3.x, aw, acc[12]); acc[13] = fmaf(w3.y, aw, acc[13]);
                    acc[14] = fmaf(w3.z, aw, acc[14]); acc[15] = fmaf(w3.w, aw, acc[15]);
                }
            }
            #pragma unroll
            for (int a = 0; a < CH; ++a)
                if (a < cn) sQ[a*AST + m] = acc[a];
        }

        // GEMM1': emb[ja][d] = sum_i Sa[i][a] * x[i][d]  (all 256, d=tid)
        {
            const int d = tid;
            float acc[CH];
            #pragma unroll
            for (int a = 0; a < CH; ++a) acc[a] = 0.0f;
            for (int i0 = 0; i0 < NN; i0 += 8) {
                float xv[8];
                #pragma unroll
                for (int u = 0; u < 8; ++u)
                    xv[u] = xB[(size_t)(i0 + u) * DD + d];
                #pragma unroll
                for (int u = 0; u < 8; ++u) {
                    const int i = i0 + u;
                    const float4 w0 = *reinterpret_cast<float4*>(&sSa[i*SST + 0]);
                    const float4 w1 = *reinterpret_cast<float4*>(&sSa[i*SST + 4]);
                    const float4 w2 = *reinterpret_cast<float4*>(&sSa[i*SST + 8]);
                    const float4 w3 = *reinterpret_cast<float4*>(&sSa[i*SST + 12]);
                    const float xu = xv[u];
                    acc[0]  = fmaf(w0.x, xu, acc[0]);  acc[1]  = fmaf(w0.y, xu, acc[1]);
                    acc[2]  = fmaf(w0.z, xu, acc[2]);  acc[3]  = fmaf(w0.w, xu, acc[3]);
                    acc[4]  = fmaf(w1.x, xu, acc[4]);  acc[5]  = fmaf(w1.y, xu, acc[5]);
                    acc[6]  = fmaf(w1.z, xu, acc[6]);  acc[7]  = fmaf(w1.w, xu, acc[7]);
                    acc[8]  = fmaf(w2.x, xu, acc[8]);  acc[9]  = fmaf(w2.y, xu, acc[9]);
                    acc[10] = fmaf(w2.z, xu, acc[10]); acc[11] = fmaf(w2.w, xu, acc[11]);
                    acc[12] = fmaf(w3.x, xu, acc[12]); acc[13] = fmaf(w3.y, xu, acc[13]);
                    acc[14] = fmaf(w3.z, xu, acc[14]); acc[15] = fmaf(w3.w, xu, acc[15]);
                }
            }
            #pragma unroll
            for (int a = 0; a < CH; ++a)
                if (a < cn) oE[(size_t)s_ac[an0 + a] * DD + d] = acc[a];
        }
        __syncthreads();   // sQ ready; sSa reads below

        // GEMM3: new_adj[ja][jb] = sum_m Q[a][m] * S[m][jb]
        if (nch == 1) {
            const int a  = tid >> 4;
            const int bq = tid & 15;
            float v = 0.0f;
            #pragma unroll 4
            for (int m = 0; m < NN; ++m)
                v = fmaf(sQ[a*AST + m], sSa[m*SST + bq], v);
            if (a < cn && bq < cn)
                oA[(size_t)s_ac[a] * NN + s_ac[bq]] = v;
        } else {
            for (int bc = 0; bc < nch; ++bc) {
                const int bn0 = bc * CH;
                int bn = K - bn0; if (bn > CH) bn = CH;
                __syncthreads();
                if (tid < NN) {
                    const int i = tid;
                    const float* ar = aB + (size_t)i * NN;
                    const float rv = s_riv[i];
                    #pragma unroll
                    for (int bq = 0; bq < CH; ++bq) {
                        float v = 0.0f;
                        if (bq < bn) {
                            int j = s_ac[bn0 + bq];
                            v = rv * (ar[j] + ((i == j) ? 1.0f : 0.0f)) * s_wa[j];
                        }
                        sSa[i*SST + bq] = v;
                    }
                }
                __syncthreads();
                const int a  = tid >> 4;
                const int bq = tid & 15;
                float v = 0.0f;
                #pragma unroll 4
                for (int m = 0; m < NN; ++m)
                    v = fmaf(sQ[a*AST + m], sSa[m*SST + bq], v);
                if (a < cn && bq < bn)
                    oA[(size_t)s_ac[an0 + a] * NN + s_ac[bn0 + bq]] = v;
            }
        }
    }
}

extern "C" void kernel_launch(void* const* d_in, const int* in_sizes, int n_in,
                              void* d_out, int out_size)
{
    const float* x    = (const float*)d_in[0];   // [B,128,256]
    const float* adj  = (const float*)d_in[1];   // [B,128,128]
    const int*   head = (const int*)  d_in[2];   // [B,512]
    const float* lw   = (const float*)d_in[3];   // [1,256]
    const float* bs   = (const float*)d_in[4];   // [1]

    const int B = in_sizes[0] / (NN * DD);       // 512

    float* out_emb = (float*)d_out;                       // [B,128,256]
    float* out_adj = out_emb + (size_t)B * NN * DD;       // [B,128,128]

    k1_stats<<<B, THREADS>>>(x, adj, lw);
    k2_main <<<B, THREADS>>>(x, adj, head, bs, out_emb, out_adj);
}